// round 6
// baseline (speedup 1.0000x reference)
#include <cuda_runtime.h>

// ---------------------------------------------------------------------------
// Quantum multi-head attention, NQ=4, DIM=16, B=32, S=2048.
// Circuit trick: with only RX gates, amp(i) = (-i)^popcount(i) * u_i, u real.
// RX becomes a real Givens rotation on (u_i, u_j); CNOT permutes u; probs = u^2.
// K1: per-token circuits -> Q(pre-scaled by log2e/2), K, V (3x parallel).
// K2: attention partials, scalar FFMA inner loop, QPT=4, KSPLIT=8,
//     no-max softmax (|score| <= 2 since |Q_i|,|K_i| <= 1).
// K3: combine partials, normalize, final circuit -> out.
// ---------------------------------------------------------------------------

#define B 32
#define S 2048
#define NTOK (B * S)          // 65536
#define KSPLIT 8
#define KCHUNK (S / KSPLIT)   // 256 keys per block
#define QPT 4                 // queries per thread
#define QTILE (128 * QPT)     // 512 queries per block

__device__ float g_Q[NTOK * 4];
__device__ float g_K[NTOK * 4];
__device__ float g_V[NTOK * 4];
__device__ float4 g_p0[NTOK * KSPLIT];   // (ssum, a0, a1, a2)
__device__ float  g_p1[NTOK * KSPLIT];   // a3

__device__ __forceinline__ float ex2_fast(float x) {
    float y;
    asm("ex2.approx.f32 %0, %1;" : "=f"(y) : "f"(x));
    return y;
}

// Real Givens rotation pair update for RX on amplitude-mask M.
// u_i' = c*u_i - s*u_j ; u_j' = c*u_j + s*u_i   (j = i|M, i has bit clear)
template <int M>
__device__ __forceinline__ void rx_real(float u[16], float c, float s) {
#pragma unroll
    for (int i = 0; i < 16; ++i) {
        if (i & M) continue;
        const int j = i | M;
        float ui = u[i], uj = u[j];
        u[i] = c * ui - s * uj;
        u[j] = c * uj + s * ui;
    }
}

// Full circuit in real arithmetic: RX(angles) x4, RX(weights) x4, CNOT ring,
// then <Z_q>. ac/as = cos/sin(angle/2), wc/ws = cos/sin(weight/2).
__device__ __forceinline__ void run_circuit(const float ac[4], const float as_[4],
                                            const float wc[4], const float ws[4],
                                            float out[4]) {
    float u[16];
#pragma unroll
    for (int i = 0; i < 16; ++i) u[i] = 0.0f;
    u[0] = 1.0f;

    rx_real<8>(u, ac[0], as_[0]);
    rx_real<4>(u, ac[1], as_[1]);
    rx_real<2>(u, ac[2], as_[2]);
    rx_real<1>(u, ac[3], as_[3]);
    rx_real<8>(u, wc[0], ws[0]);
    rx_real<4>(u, wc[1], ws[1]);
    rx_real<2>(u, wc[2], ws[2]);
    rx_real<1>(u, wc[3], ws[3]);

    // CNOT ring: pure permutation of amplitudes (register renames).
#define SWAP_AMP(a, b) { float t = u[a]; u[a] = u[b]; u[b] = t; }
    SWAP_AMP(8, 12)  SWAP_AMP(9, 13)  SWAP_AMP(10, 14) SWAP_AMP(11, 15)   // CNOT(0,1)
    SWAP_AMP(4, 6)   SWAP_AMP(5, 7)   SWAP_AMP(12, 14) SWAP_AMP(13, 15)   // CNOT(1,2)
    SWAP_AMP(2, 3)   SWAP_AMP(6, 7)   SWAP_AMP(10, 11) SWAP_AMP(14, 15)   // CNOT(2,3)
    SWAP_AMP(1, 9)   SWAP_AMP(3, 11)  SWAP_AMP(5, 13)  SWAP_AMP(7, 15)    // CNOT(3,0)
#undef SWAP_AMP

    float p[16];
#pragma unroll
    for (int i = 0; i < 16; ++i) p[i] = u[i] * u[i];

    // Shared-tree signed sums: o_q = sum_i (-1)^{bit_q(i)} p_i.
    float a0 = p[0] + p[1],   d0 = p[0] - p[1];
    float a1 = p[2] + p[3],   d1 = p[2] - p[3];
    float a2 = p[4] + p[5],   d2 = p[4] - p[5];
    float a3 = p[6] + p[7],   d3 = p[6] - p[7];
    float a4 = p[8] + p[9],   d4 = p[8] - p[9];
    float a5 = p[10] + p[11], d5 = p[10] - p[11];
    float a6 = p[12] + p[13], d6 = p[12] - p[13];
    float a7 = p[14] + p[15], d7 = p[14] - p[15];
    // mask 1 (LSB):
    out[3] = ((d0 + d1) + (d2 + d3)) + ((d4 + d5) + (d6 + d7));
    float b0 = a0 + a1, e0 = a0 - a1;
    float b1 = a2 + a3, e1 = a2 - a3;
    float b2 = a4 + a5, e2 = a4 - a5;
    float b3 = a6 + a7, e3 = a6 - a7;
    // mask 2:
    out[2] = (e0 + e1) + (e2 + e3);
    float c0 = b0 + b1, f0 = b0 - b1;
    float c1 = b2 + b3, f1 = b2 - b3;
    // mask 4:
    out[1] = f0 + f1;
    // mask 8:
    out[0] = c0 - c1;
}

// ---------------------------------------------------------------------------
// K1: token circuits. blockIdx.y selects which of {Q,K,V}.
// Q is pre-scaled by (1/sqrt(E)) * log2(e).
// ---------------------------------------------------------------------------
__global__ void __launch_bounds__(128) qkv_kernel(const float4* __restrict__ x,
                                                  const float* __restrict__ wQ,
                                                  const float* __restrict__ wK,
                                                  const float* __restrict__ wV) {
    const int t = blockIdx.x * 128 + threadIdx.x;
    const int which = blockIdx.y;

    float4 a = x[t];
    float ac[4], as_[4];
    __sincosf(0.5f * a.x, &as_[0], &ac[0]);
    __sincosf(0.5f * a.y, &as_[1], &ac[1]);
    __sincosf(0.5f * a.z, &as_[2], &ac[2]);
    __sincosf(0.5f * a.w, &as_[3], &ac[3]);

    const float* w = (which == 0) ? wQ : (which == 1) ? wK : wV;
    float* dst     = (which == 0) ? g_Q : (which == 1) ? g_K : g_V;
    const float scale = (which == 0) ? (0.5f * 1.4426950408889634f) : 1.0f;

    float wc[4], ws[4], o[4];
#pragma unroll
    for (int q = 0; q < 4; ++q) __sincosf(0.5f * __ldg(&w[q]), &ws[q], &wc[q]);
    run_circuit(ac, as_, wc, ws, o);
    reinterpret_cast<float4*>(dst)[t] =
        make_float4(o[0] * scale, o[1] * scale, o[2] * scale, o[3] * scale);
}

// ---------------------------------------------------------------------------
// K2: attention partials. grid (B, S/QTILE, KSPLIT), 128 threads.
// Thread owns queries qb + t + {0,128,256,384}; KCHUNK keys via smem.
// Scalar FFMA math; 4 independent chains for ILP.
// ---------------------------------------------------------------------------
__global__ void __launch_bounds__(128) attn_kernel() {
    __shared__ float4 sk[KCHUNK];
    __shared__ float4 sv[KCHUNK];

    const int b  = blockIdx.x;
    const int qb = blockIdx.y * QTILE;
    const int kq = blockIdx.z;
    const int t  = threadIdx.x;

    const float4* __restrict__ Kb =
        reinterpret_cast<const float4*>(g_K) + b * S + kq * KCHUNK;
    const float4* __restrict__ Vb =
        reinterpret_cast<const float4*>(g_V) + b * S + kq * KCHUNK;

#pragma unroll
    for (int i = 0; i < KCHUNK / 128; ++i) {
        sk[i * 128 + t] = Kb[i * 128 + t];
        sv[i * 128 + t] = Vb[i * 128 + t];
    }

    float4 q[QPT];
    float a0[QPT], a1[QPT], a2[QPT], a3[QPT], ss[QPT];
#pragma unroll
    for (int j = 0; j < QPT; ++j) {
        q[j] = reinterpret_cast<const float4*>(g_Q)[b * S + qb + t + j * 128];
        a0[j] = a1[j] = a2[j] = a3[j] = ss[j] = 0.f;
    }

    __syncthreads();

#pragma unroll 4
    for (int k = 0; k < KCHUNK; ++k) {
        float4 kk = sk[k];      // LDS.128 broadcast
        float4 vv = sv[k];
#pragma unroll
        for (int j = 0; j < QPT; ++j) {
            float d = fmaf(q[j].x, kk.x,
                      fmaf(q[j].y, kk.y,
                      fmaf(q[j].z, kk.z, q[j].w * kk.w)));
            float e = ex2_fast(d);
            ss[j] += e;
            a0[j] = fmaf(e, vv.x, a0[j]);
            a1[j] = fmaf(e, vv.y, a1[j]);
            a2[j] = fmaf(e, vv.z, a2[j]);
            a3[j] = fmaf(e, vv.w, a3[j]);
        }
    }

    const int base = ((b * KSPLIT + kq) << 11) + qb + t;   // ((b*KSPLIT+kq)*S + q)
#pragma unroll
    for (int j = 0; j < QPT; ++j) {
        g_p0[base + j * 128] = make_float4(ss[j], a0[j], a1[j], a2[j]);
        g_p1[base + j * 128] = a3[j];
    }
}

// ---------------------------------------------------------------------------
// K3: combine KSPLIT partials, normalize, final circuit -> out.
// ---------------------------------------------------------------------------
__global__ void __launch_bounds__(128) reduce_kernel(const float* __restrict__ wC,
                                                     float4* __restrict__ out) {
    int g = blockIdx.x * 128 + threadIdx.x;  // global query 0..NTOK-1
    int b = g >> 11;
    int q = g & (S - 1);

    float ssum = 0.f, a0 = 0.f, a1 = 0.f, a2 = 0.f, a3 = 0.f;
#pragma unroll
    for (int kq = 0; kq < KSPLIT; ++kq) {
        int idx = ((b * KSPLIT + kq) << 11) + q;
        float4 p = g_p0[idx];
        ssum += p.x; a0 += p.y; a1 += p.z; a2 += p.w;
        a3 += g_p1[idx];
    }
    float inv = 1.0f / ssum;

    float cc[4], cs[4], wc[4], ws[4], o[4];
    __sincosf(0.5f * a0 * inv, &cs[0], &cc[0]);
    __sincosf(0.5f * a1 * inv, &cs[1], &cc[1]);
    __sincosf(0.5f * a2 * inv, &cs[2], &cc[2]);
    __sincosf(0.5f * a3 * inv, &cs[3], &cc[3]);
#pragma unroll
    for (int i = 0; i < 4; ++i) __sincosf(0.5f * __ldg(&wC[i]), &ws[i], &wc[i]);
    run_circuit(cc, cs, wc, ws, o);

    out[g] = make_float4(o[0], o[1], o[2], o[3]);
}

// ---------------------------------------------------------------------------
extern "C" void kernel_launch(void* const* d_in, const int* in_sizes, int n_in,
                              void* d_out, int out_size) {
    (void)in_sizes; (void)n_in; (void)out_size;
    const float4* x  = (const float4*)d_in[0];
    const float*  wQ = (const float*)d_in[1];
    const float*  wK = (const float*)d_in[2];
    const float*  wV = (const float*)d_in[3];
    const float*  wC = (const float*)d_in[4];

    qkv_kernel<<<dim3(NTOK / 128, 3), 128>>>(x, wQ, wK, wV);
    attn_kernel<<<dim3(B, S / QTILE, KSPLIT), 128>>>();
    reduce_kernel<<<NTOK / 128, 128>>>(wC, (float4*)d_out);
}

// round 9
// speedup vs baseline: 1.0252x; 1.0252x over previous
#include <cuda_runtime.h>

// ---------------------------------------------------------------------------
// Quantum multi-head attention, NQ=4, DIM=16, B=32, S=2048.
// Real-amplitude circuit trick: amp(i) = (-i)^popcount(i) * u_i with u real;
// RX = real Givens rotation, CNOT = permutation, probs = u^2.
// K1: per-token circuits -> Q(pre-scaled by log2e/2), K, V (3x parallel).
// K2: attention partials: packed f32x2 math (FFMA2), QPT=8, KSPLIT=16,
//     no-max softmax (|score| <= 2.9 in exp2 domain, always safe).
// K3: combine 16 partials, normalize, final circuit -> out.
// ---------------------------------------------------------------------------

#define B 32
#define S 2048
#define NTOK (B * S)          // 65536
#define KSPLIT 16
#define KCHUNK (S / KSPLIT)   // 128 keys per block
#define QPT 8                 // queries per thread
#define QTILE (128 * QPT)     // 1024 queries per block

__device__ float g_Q[NTOK * 4];
__device__ float g_K[NTOK * 4];
__device__ float g_V[NTOK * 4];
__device__ float4 g_p0[NTOK * KSPLIT];   // (ssum, a0, a1, a2)
__device__ float  g_p1[NTOK * KSPLIT];   // a3

typedef unsigned long long u64;

__device__ __forceinline__ float ex2_fast(float x) {
    float y;
    asm("ex2.approx.f32 %0, %1;" : "=f"(y) : "f"(x));
    return y;
}
__device__ __forceinline__ u64 mul2(u64 a, u64 b) {
    u64 d; asm("mul.rn.f32x2 %0,%1,%2;" : "=l"(d) : "l"(a), "l"(b)); return d;
}
__device__ __forceinline__ u64 fma2(u64 a, u64 b, u64 c) {
    u64 d; asm("fma.rn.f32x2 %0,%1,%2,%3;" : "=l"(d) : "l"(a), "l"(b), "l"(c)); return d;
}
__device__ __forceinline__ float2 u2f(u64 u) {
    float2 f; asm("mov.b64 {%0,%1}, %2;" : "=f"(f.x), "=f"(f.y) : "l"(u)); return f;
}
__device__ __forceinline__ u64 f2u(float a, float b) {
    u64 u; asm("mov.b64 %0, {%1,%2};" : "=l"(u) : "f"(a), "f"(b)); return u;
}

// Real Givens rotation for RX on amplitude-mask M.
template <int M>
__device__ __forceinline__ void rx_real(float u[16], float c, float s) {
#pragma unroll
    for (int i = 0; i < 16; ++i) {
        if (i & M) continue;
        const int j = i | M;
        float ui = u[i], uj = u[j];
        u[i] = c * ui - s * uj;
        u[j] = c * uj + s * ui;
    }
}

__device__ __forceinline__ void run_circuit(const float ac[4], const float as_[4],
                                            const float wc[4], const float ws[4],
                                            float out[4]) {
    float u[16];
#pragma unroll
    for (int i = 0; i < 16; ++i) u[i] = 0.0f;
    u[0] = 1.0f;

    rx_real<8>(u, ac[0], as_[0]);
    rx_real<4>(u, ac[1], as_[1]);
    rx_real<2>(u, ac[2], as_[2]);
    rx_real<1>(u, ac[3], as_[3]);
    rx_real<8>(u, wc[0], ws[0]);
    rx_real<4>(u, wc[1], ws[1]);
    rx_real<2>(u, wc[2], ws[2]);
    rx_real<1>(u, wc[3], ws[3]);

#define SWAP_AMP(a, b) { float t = u[a]; u[a] = u[b]; u[b] = t; }
    SWAP_AMP(8, 12)  SWAP_AMP(9, 13)  SWAP_AMP(10, 14) SWAP_AMP(11, 15)   // CNOT(0,1)
    SWAP_AMP(4, 6)   SWAP_AMP(5, 7)   SWAP_AMP(12, 14) SWAP_AMP(13, 15)   // CNOT(1,2)
    SWAP_AMP(2, 3)   SWAP_AMP(6, 7)   SWAP_AMP(10, 11) SWAP_AMP(14, 15)   // CNOT(2,3)
    SWAP_AMP(1, 9)   SWAP_AMP(3, 11)  SWAP_AMP(5, 13)  SWAP_AMP(7, 15)    // CNOT(3,0)
#undef SWAP_AMP

    float p[16];
#pragma unroll
    for (int i = 0; i < 16; ++i) p[i] = u[i] * u[i];

    float a0 = p[0] + p[1],   d0 = p[0] - p[1];
    float a1 = p[2] + p[3],   d1 = p[2] - p[3];
    float a2 = p[4] + p[5],   d2 = p[4] - p[5];
    float a3 = p[6] + p[7],   d3 = p[6] - p[7];
    float a4 = p[8] + p[9],   d4 = p[8] - p[9];
    float a5 = p[10] + p[11], d5 = p[10] - p[11];
    float a6 = p[12] + p[13], d6 = p[12] - p[13];
    float a7 = p[14] + p[15], d7 = p[14] - p[15];
    out[3] = ((d0 + d1) + (d2 + d3)) + ((d4 + d5) + (d6 + d7));
    float b0 = a0 + a1, e0 = a0 - a1;
    float b1 = a2 + a3, e1 = a2 - a3;
    float b2 = a4 + a5, e2 = a4 - a5;
    float b3 = a6 + a7, e3 = a6 - a7;
    out[2] = (e0 + e1) + (e2 + e3);
    float c0 = b0 + b1, f0 = b0 - b1;
    float c1 = b2 + b3, f1 = b2 - b3;
    out[1] = f0 + f1;
    out[0] = c0 - c1;
}

// ---------------------------------------------------------------------------
// K1: token circuits. blockIdx.y selects which of {Q,K,V}.
// ---------------------------------------------------------------------------
__global__ void __launch_bounds__(128) qkv_kernel(const float4* __restrict__ x,
                                                  const float* __restrict__ wQ,
                                                  const float* __restrict__ wK,
                                                  const float* __restrict__ wV) {
    const int t = blockIdx.x * 128 + threadIdx.x;
    const int which = blockIdx.y;

    float4 a = x[t];
    float ac[4], as_[4];
    __sincosf(0.5f * a.x, &as_[0], &ac[0]);
    __sincosf(0.5f * a.y, &as_[1], &ac[1]);
    __sincosf(0.5f * a.z, &as_[2], &ac[2]);
    __sincosf(0.5f * a.w, &as_[3], &ac[3]);

    const float* w = (which == 0) ? wQ : (which == 1) ? wK : wV;
    float* dst     = (which == 0) ? g_Q : (which == 1) ? g_K : g_V;
    const float scale = (which == 0) ? (0.5f * 1.4426950408889634f) : 1.0f;

    float wc[4], ws[4], o[4];
#pragma unroll
    for (int q = 0; q < 4; ++q) __sincosf(0.5f * __ldg(&w[q]), &ws[q], &wc[q]);
    run_circuit(ac, as_, wc, ws, o);
    reinterpret_cast<float4*>(dst)[t] =
        make_float4(o[0] * scale, o[1] * scale, o[2] * scale, o[3] * scale);
}

// ---------------------------------------------------------------------------
// K2: attention partials. grid (B, S/QTILE, KSPLIT), 128 threads.
// Thread owns queries qb + t + j*128, j=0..7; KCHUNK keys via smem.
// Packed f32x2 (FFMA2) math; 8 independent chains for ILP.
// ---------------------------------------------------------------------------
__global__ void __launch_bounds__(128) attn_kernel() {
    __shared__ ulonglong2 sk[KCHUNK];
    __shared__ ulonglong2 sv[KCHUNK];

    const int b  = blockIdx.x;
    const int qb = blockIdx.y * QTILE;
    const int kq = blockIdx.z;
    const int t  = threadIdx.x;

    const ulonglong2* __restrict__ Kb =
        reinterpret_cast<const ulonglong2*>(g_K) + b * S + kq * KCHUNK;
    const ulonglong2* __restrict__ Vb =
        reinterpret_cast<const ulonglong2*>(g_V) + b * S + kq * KCHUNK;

    if (t < KCHUNK) {          // KCHUNK == 128
        sk[t] = Kb[t];
        sv[t] = Vb[t];
    }

    u64 qlo[QPT], qhi[QPT];
    u64 acc0[QPT], acc1[QPT];
    float ss[QPT];
#pragma unroll
    for (int j = 0; j < QPT; ++j) {
        float4 qv = reinterpret_cast<const float4*>(g_Q)[b * S + qb + t + j * 128];
        qlo[j] = f2u(qv.x, qv.y);
        qhi[j] = f2u(qv.z, qv.w);
        acc0[j] = f2u(0.f, 0.f);
        acc1[j] = f2u(0.f, 0.f);
        ss[j] = 0.f;
    }

    __syncthreads();

#pragma unroll 2
    for (int k = 0; k < KCHUNK; ++k) {
        ulonglong2 kk = sk[k];      // LDS.128 broadcast
        ulonglong2 vv = sv[k];
#pragma unroll
        for (int j = 0; j < QPT; ++j) {
            u64 d = fma2(qhi[j], kk.y, mul2(qlo[j], kk.x));
            float2 df = u2f(d);
            float e = ex2_fast(df.x + df.y);
            u64 ee = f2u(e, e);
            acc0[j] = fma2(ee, vv.x, acc0[j]);
            acc1[j] = fma2(ee, vv.y, acc1[j]);
            ss[j] += e;
        }
    }

    const int base = ((b * KSPLIT + kq) << 11) + qb + t;   // ((b*KSPLIT+kq)*S + q)
#pragma unroll
    for (int j = 0; j < QPT; ++j) {
        float2 a0 = u2f(acc0[j]), a1 = u2f(acc1[j]);
        g_p0[base + j * 128] = make_float4(ss[j], a0.x, a0.y, a1.x);
        g_p1[base + j * 128] = a1.y;
    }
}

// ---------------------------------------------------------------------------
// K3: combine KSPLIT partials, normalize, final circuit -> out.
// ---------------------------------------------------------------------------
__global__ void __launch_bounds__(128) reduce_kernel(const float* __restrict__ wC,
                                                     float4* __restrict__ out) {
    int g = blockIdx.x * 128 + threadIdx.x;  // global query 0..NTOK-1
    int b = g >> 11;
    int q = g & (S - 1);

    float ssum = 0.f, a0 = 0.f, a1 = 0.f, a2 = 0.f, a3 = 0.f;
#pragma unroll
    for (int kq = 0; kq < KSPLIT; ++kq) {
        int idx = ((b * KSPLIT + kq) << 11) + q;
        float4 p = g_p0[idx];
        ssum += p.x; a0 += p.y; a1 += p.z; a2 += p.w;
        a3 += g_p1[idx];
    }
    float inv = 1.0f / ssum;

    float cc[4], cs[4], wc[4], ws[4], o[4];
    __sincosf(0.5f * a0 * inv, &cs[0], &cc[0]);
    __sincosf(0.5f * a1 * inv, &cs[1], &cc[1]);
    __sincosf(0.5f * a2 * inv, &cs[2], &cc[2]);
    __sincosf(0.5f * a3 * inv, &cs[3], &cc[3]);
#pragma unroll
    for (int i = 0; i < 4; ++i) __sincosf(0.5f * __ldg(&wC[i]), &ws[i], &wc[i]);
    run_circuit(cc, cs, wc, ws, o);

    out[g] = make_float4(o[0], o[1], o[2], o[3]);
}

// ---------------------------------------------------------------------------
extern "C" void kernel_launch(void* const* d_in, const int* in_sizes, int n_in,
                              void* d_out, int out_size) {
    (void)in_sizes; (void)n_in; (void)out_size;
    const float4* x  = (const float4*)d_in[0];
    const float*  wQ = (const float*)d_in[1];
    const float*  wK = (const float*)d_in[2];
    const float*  wV = (const float*)d_in[3];
    const float*  wC = (const float*)d_in[4];

    qkv_kernel<<<dim3(NTOK / 128, 3), 128>>>(x, wQ, wK, wV);
    attn_kernel<<<dim3(B, S / QTILE, KSPLIT), 128>>>();
    reduce_kernel<<<NTOK / 128, 128>>>(wC, (float4*)d_out);
}